// round 15
// baseline (speedup 1.0000x reference)
#include <cuda_runtime.h>
#include <cuda_bf16.h>
#include <cstdint>

// LinearMultiheadSplit: out[n] = x[n] @ (W[head] + 0.1*D[head*4+split]) + bias[head]
// N=1024, IN=OUT=512, 32 heads x 4 splits -> 128 combos.
//
// v8: warp-private cp.async rings (v6's byte-in-flight mechanism without v6's
// block-barrier serialization; v7 proved register pipelines cap at MLP~6 due to
// 6-slot SASS scoreboard sharing).
//  - 256 blocks (2 col-tiles x 128 combos), 256 threads = 8 warps
//  - warp owns 64 cols x 256 k; streams its W/D via a private 4-stage x 4-k
//    smem ring (cp.async.cg). Sync = wait_group + __syncwarp ONLY.
//  - k-split in-block (warps 0-3: k[0,256), warps 4-7: k[256,512)); smem reduce
//  - packed fma.rn.f32x2: 2 samples per 64-bit lane, CHUNK=16 zero-padded

#define N_SAMPLES 1024
#define IN_F      512
#define OUT_F     512
#define N_COMBO   128
#define THREADS   256
#define KHALF     256
#define CHUNK     16
#define KSTAGE    4
#define NSTAGES   4
#define STAGES    (KHALF / KSTAGE)          // 64
#define WSTAGE_B  (KSTAGE * 64 * 4)         // 1024 B per tensor per stage
#define WRING_B   (NSTAGES * WSTAGE_B)      // 4096 B per tensor per warp

// dynamic smem layout (16B-aligned)
#define OFF_CNT   0
#define OFF_LIST  16                               // short[1024] = 2048
#define OFF_XS    2064                             // float[512*16] = 32768 (also `red`)
#define OFF_SW    (OFF_XS + IN_F * CHUNK * 4)      // 34832, 8 warps * 4096
#define OFF_SD    (OFF_SW + 8 * WRING_B)           // 67600
#define SMEM_TOTAL (OFF_SD + 8 * WRING_B)          // 100368 -> 2 blocks/SM

__device__ __forceinline__ unsigned long long dup2(float v) {
    unsigned long long r; unsigned u = __float_as_uint(v);
    asm("mov.b64 %0, {%1, %1};" : "=l"(r) : "r"(u));
    return r;
}
__device__ __forceinline__ unsigned long long fma2(unsigned long long a,
                                                   unsigned long long b,
                                                   unsigned long long c) {
    unsigned long long d;
    asm("fma.rn.f32x2 %0, %1, %2, %3;" : "=l"(d) : "l"(a), "l"(b), "l"(c));
    return d;
}
__device__ __forceinline__ void unpack2(unsigned long long v, float& lo, float& hi) {
    unsigned a, b;
    asm("mov.b64 {%0, %1}, %2;" : "=r"(a), "=r"(b) : "l"(v));
    lo = __uint_as_float(a); hi = __uint_as_float(b);
}
__device__ __forceinline__ void cp16(unsigned dst, const void* src) {
    asm volatile("cp.async.cg.shared.global [%0], [%1], 16;"
                 :: "r"(dst), "l"(src) : "memory");
}
template <int N>
__device__ __forceinline__ void cp_wait() {
    asm volatile("cp.async.wait_group %0;" :: "n"(N) : "memory");
}

// Issue one 4-k stage of this warp's W and D slices into its private ring.
// Stage = 4 rows x 256 B (64 cols), row-major in smem. 2 x 16B per thread per tensor.
__device__ __forceinline__ void issue_stage(unsigned swr, unsigned sdr,
                                            const float* wsrc0, const float* dsrc0,
                                            int st, int lane)
{
    const unsigned slot = (unsigned)(st & (NSTAGES - 1)) * WSTAGE_B;
    const float* ws = wsrc0 + (size_t)st * (KSTAGE * OUT_F);
    const float* ds = dsrc0 + (size_t)st * (KSTAGE * OUT_F);
#pragma unroll
    for (int i = 0; i < 2; ++i) {
        int chunk  = lane + i * 32;          // 0..63 (16B units)
        int row    = chunk >> 4;             // 0..3
        int col4   = (chunk & 15) * 4;       // float offset within row
        unsigned doff = slot + (unsigned)chunk * 16;
        cp16(swr + doff, ws + row * OUT_F + col4);
        cp16(sdr + doff, ds + row * OUT_F + col4);
    }
    asm volatile("cp.async.commit_group;" ::: "memory");
}

// Compute one 4-k stage from the warp's ring. 16 samples (8 f32x2 pairs) x 2 cols.
__device__ __forceinline__ void compute_stage(unsigned swr, unsigned sdr,
                                              unsigned xk0, int st, int lane,
                                              unsigned long long* acc)
{
    const unsigned slot = (unsigned)(st & (NSTAGES - 1)) * WSTAGE_B;
    const unsigned wa = swr + slot + (unsigned)lane * 8;
    const unsigned da = sdr + slot + (unsigned)lane * 8;
    const unsigned xk = xk0 + (unsigned)(st * KSTAGE) * (CHUNK * 4);
#pragma unroll
    for (int j = 0; j < KSTAGE; ++j) {
        float2 w2, d2;
        asm volatile("ld.shared.v2.f32 {%0,%1},[%2];"
                     : "=f"(w2.x), "=f"(w2.y) : "r"(wa + (unsigned)(j * 256)));
        asm volatile("ld.shared.v2.f32 {%0,%1},[%2];"
                     : "=f"(d2.x), "=f"(d2.y) : "r"(da + (unsigned)(j * 256)));
        float wv0 = fmaf(d2.x, 0.1f, w2.x);
        float wv1 = fmaf(d2.y, 0.1f, w2.y);
        unsigned long long wva = dup2(wv0);
        unsigned long long wvb = dup2(wv1);

        unsigned a = xk + (unsigned)j * (CHUNK * 4);
        unsigned long long xp[8];
#pragma unroll
        for (int p = 0; p < 8; p += 2) {
            asm volatile("ld.shared.v2.b64 {%0,%1},[%2];"
                         : "=l"(xp[p]), "=l"(xp[p + 1]) : "r"(a + (unsigned)(8 * p)));
        }
#pragma unroll
        for (int p = 0; p < 8; ++p) {
            acc[p]     = fma2(xp[p], wva, acc[p]);
            acc[8 + p] = fma2(xp[p], wvb, acc[8 + p]);
        }
    }
}

__global__ void __launch_bounds__(THREADS, 2)
lms_kernel(const float* __restrict__ X,
           const int* __restrict__ hix,
           const int* __restrict__ six,
           const float* __restrict__ W,
           const float* __restrict__ D,
           const float* __restrict__ B,
           float* __restrict__ out)
{
    extern __shared__ __align__(16) char smem[];
    int*    s_cnt  = (int*)(smem + OFF_CNT);
    short*  s_list = (short*)(smem + OFF_LIST);
    float*  xs     = (float*)(smem + OFF_XS);
    float2* red2   = (float2*)(smem + OFF_XS);     // aliases xs (dead post-compute)

    const unsigned smem_u32 = (unsigned)__cvta_generic_to_shared(smem);

    const int tid  = threadIdx.x;
    const int lane = tid & 31;
    const int w    = tid >> 5;            // warp 0..7
    const int cw   = w & 3;               // col sub-tile 0..3 (64 cols each)
    const int kg   = w >> 2;              // k-group 0/1
    const int g    = blockIdx.y;          // combo
    const int h    = g >> 2;
    const int sp   = g & 3;
    const int cb   = blockIdx.x * 256 + cw * 64;   // warp col base
    const int c0   = cb + lane * 2;                 // thread's 2 cols
    const int tcol = cw * 32 + lane;                // float2 col index 0..127

    // ---- Phase A: build sample list for this combo ----
    if (tid == 0) *s_cnt = 0;
    __syncthreads();
    for (int n = tid; n < N_SAMPLES; n += THREADS) {
        if (hix[n] == h && six[n] == sp) {
            int p = atomicAdd(s_cnt, 1);
            s_list[p] = (short)n;
        }
    }
    __syncthreads();
    const int m = *s_cnt;
    if (m == 0) return;                   // uniform across block; nothing issued

    // warp's gmem slices: k-half kg, cols [cb, cb+64)
    const float* wsrc0 = W + (size_t)h * (IN_F * OUT_F)
                           + (size_t)(kg * KHALF) * OUT_F + cb;
    const float* dsrc0 = D + (size_t)g * (IN_F * OUT_F)
                           + (size_t)(kg * KHALF) * OUT_F + cb;
    const float2 bv = *(const float2*)(B + h * OUT_F + c0);

    const unsigned swr = smem_u32 + OFF_SW + (unsigned)w * WRING_B;
    const unsigned sdr = smem_u32 + OFF_SD + (unsigned)w * WRING_B;
    const unsigned xk0 = smem_u32 + OFF_XS + (unsigned)(kg * KHALF) * (CHUNK * 4);

    // xs staging mapping: s = tid&15 (sample slot), q0 = tid>>4 (float4 base)
    const int s  = tid & 15;
    const int q0 = tid >> 4;              // 0..15

    // Nearly always a single pass (P[m>16] ~ 0.4% per combo).
    for (int base = 0; base < m; base += CHUNK) {
        // prologue: fill this warp's ring (overlaps with xs staging below)
#pragma unroll
        for (int st = 0; st < NSTAGES; ++st)
            issue_stage(swr, sdr, wsrc0, dsrc0, st, lane);

        // ---- stage x chunk transposed into smem (zero-padded) ----
        const int  sg    = base + s;
        const bool valid = sg < m;
        const float4* xrow =
            valid ? (const float4*)(X + (size_t)s_list[sg] * IN_F) : (const float4*)X;
#pragma unroll
        for (int i = 0; i < 8; ++i) {
            int Q = q0 + i * 16;          // 0..127
            float4 v = valid ? __ldg(xrow + Q) : make_float4(0.f, 0.f, 0.f, 0.f);
            int k0 = Q * 4;
            xs[(k0 + 0) * CHUNK + s] = v.x;
            xs[(k0 + 1) * CHUNK + s] = v.y;
            xs[(k0 + 2) * CHUNK + s] = v.z;
            xs[(k0 + 3) * CHUNK + s] = v.w;
        }
        __syncthreads();

        // ---- warp-private pipelined k-loop: NO block barriers ----
        unsigned long long acc[16];
#pragma unroll
        for (int j = 0; j < 16; ++j) acc[j] = 0ull;

#pragma unroll 1
        for (int st = 0; st < STAGES - NSTAGES; ++st) {
            cp_wait<NSTAGES - 1>();
            __syncwarp();                     // stage st visible warp-wide
            compute_stage(swr, sdr, xk0, st, lane, acc);
            __syncwarp();                     // all lanes done reading slot
            issue_stage(swr, sdr, wsrc0, dsrc0, st + NSTAGES, lane);
        }
        cp_wait<3>(); __syncwarp();
        compute_stage(swr, sdr, xk0, STAGES - 4, lane, acc);
        cp_wait<2>(); __syncwarp();
        compute_stage(swr, sdr, xk0, STAGES - 3, lane, acc);
        cp_wait<1>(); __syncwarp();
        compute_stage(swr, sdr, xk0, STAGES - 2, lane, acc);
        cp_wait<0>(); __syncwarp();
        compute_stage(swr, sdr, xk0, STAGES - 1, lane, acc);

        // ---- reduce kg=1 -> kg=0 via red2 (aliases xs; xs dead now) ----
        __syncthreads();
        if (kg == 1) {
#pragma unroll
            for (int p = 0; p < 8; ++p) {
                float a0, a1, b0, b1;
                unpack2(acc[p],     a0, a1);   // col0: samples 2p, 2p+1
                unpack2(acc[8 + p], b0, b1);   // col1
                red2[(2 * p + 0) * 128 + tcol] = make_float2(a0, b0);
                red2[(2 * p + 1) * 128 + tcol] = make_float2(a1, b1);
            }
        }
        __syncthreads();
        if (kg == 0) {
#pragma unroll
            for (int p = 0; p < 8; ++p) {
                float a0, a1, b0, b1;
                unpack2(acc[p],     a0, a1);
                unpack2(acc[8 + p], b0, b1);
                float2 r0 = red2[(2 * p + 0) * 128 + tcol];
                float2 r1 = red2[(2 * p + 1) * 128 + tcol];
                int i0 = base + 2 * p;
                if (i0 < m) {
                    int n = s_list[i0];
                    float2 o = make_float2(a0 + r0.x + bv.x, b0 + r0.y + bv.y);
                    *(float2*)(out + (size_t)n * OUT_F + c0) = o;
                }
                if (i0 + 1 < m) {
                    int n = s_list[i0 + 1];
                    float2 o = make_float2(a1 + r1.x + bv.x, b1 + r1.y + bv.y);
                    *(float2*)(out + (size_t)n * OUT_F + c0) = o;
                }
            }
        }
        __syncthreads();                   // red/xs reuse safe for next pass
    }
}

extern "C" void kernel_launch(void* const* d_in, const int* in_sizes, int n_in,
                              void* d_out, int out_size)
{
    const float* X   = (const float*)d_in[0];
    const int*   hix = (const int*)d_in[1];
    const int*   six = (const int*)d_in[2];
    const float* W   = (const float*)d_in[3];
    const float* D   = (const float*)d_in[4];
    const float* B   = (const float*)d_in[5];
    float*       out = (float*)d_out;

    cudaFuncSetAttribute(lms_kernel,
                         cudaFuncAttributeMaxDynamicSharedMemorySize, SMEM_TOTAL);
    dim3 grid(OUT_F / 256, N_COMBO);      // (2, 128) = 256 blocks
    lms_kernel<<<grid, THREADS, SMEM_TOTAL>>>(X, hix, six, W, D, B, out);
}

// round 17
// speedup vs baseline: 1.1258x; 1.1258x over previous
#include <cuda_runtime.h>
#include <cuda_bf16.h>
#include <cstdint>

// LinearMultiheadSplit: out[n] = x[n] @ (W[head] + 0.1*D[head*4+split]) + bias[head]
// N=1024, IN=OUT=512, 32 heads x 4 splits -> 128 combos.
//
// v9: occupancy fix. All prior variants (reg pipeline, block cp.async, warp
// cp.async) pinned at ~3.1 TB/s with the one invariant being ~16 warps/SM.
//  - 8-way k-split ACROSS blocks: grid = 8 ksegs x 128 combos = 1024 blocks,
//    256 threads, ~24 warps/SM sustained (3 blocks/SM, 2.3 smooth waves)
//  - partials merged with atomicAdd; init kernel pre-writes bias
//  - thread = 2 cols x 64 k; register pipeline PIPE=4 (scoreboard caps ~6 anyway)
//  - packed fma.rn.f32x2: 2 samples per 64-bit lane; PAIRS template 4/8

#define N_SAMPLES 1024
#define IN_F      512
#define OUT_F     512
#define N_COMBO   128
#define THREADS   256
#define KSPLIT    8
#define KSEG      (IN_F / KSPLIT)   // 64 k per block
#define CHUNK     16
#define PIPE      4
#define ROWF2     (OUT_F / 2)       // 256 float2 per k-row

__device__ __forceinline__ unsigned long long dup2(float v) {
    unsigned long long r; unsigned u = __float_as_uint(v);
    asm("mov.b64 %0, {%1, %1};" : "=l"(r) : "r"(u));
    return r;
}
__device__ __forceinline__ unsigned long long fma2(unsigned long long a,
                                                   unsigned long long b,
                                                   unsigned long long c) {
    unsigned long long d;
    asm("fma.rn.f32x2 %0, %1, %2, %3;" : "=l"(d) : "l"(a), "l"(b), "l"(c));
    return d;
}
__device__ __forceinline__ void unpack2(unsigned long long v, float& lo, float& hi) {
    unsigned a, b;
    asm("mov.b64 {%0, %1}, %2;" : "=r"(a), "=r"(b) : "l"(v));
    lo = __uint_as_float(a); hi = __uint_as_float(b);
}
__device__ __forceinline__ float2 ldg2(const float2* p) {
    float2 v;
    asm volatile("ld.global.nc.v2.f32 {%0,%1}, [%2];"
                 : "=f"(v.x), "=f"(v.y) : "l"(p));
    return v;
}

// one k-step: combine W/D, broadcast-load PAIRS x-pairs from smem, accumulate
template <int PAIRS>
__device__ __forceinline__ void kstep(int k, float2 w2, float2 d2, unsigned xa,
                                      unsigned long long* acc)
{
    float wv0 = fmaf(d2.x, 0.1f, w2.x);
    float wv1 = fmaf(d2.y, 0.1f, w2.y);
    unsigned long long wva = dup2(wv0);
    unsigned long long wvb = dup2(wv1);

    unsigned a = xa + (unsigned)k * (CHUNK * 4);
    unsigned long long xp[PAIRS];
#pragma unroll
    for (int p = 0; p < PAIRS; p += 2) {
        asm volatile("ld.shared.v2.b64 {%0,%1},[%2];"
                     : "=l"(xp[p]), "=l"(xp[p + 1]) : "r"(a + (unsigned)(8 * p)));
    }
#pragma unroll
    for (int p = 0; p < PAIRS; ++p) {
        acc[p]         = fma2(xp[p], wva, acc[p]);
        acc[PAIRS + p] = fma2(xp[p], wvb, acc[PAIRS + p]);
    }
}

// 64-k pass over this block's k-segment, then atomicAdd partials to out.
template <int PAIRS>
__device__ __forceinline__ void compute_pass(
    const float2* __restrict__ wp, const float2* __restrict__ dp,
    unsigned xa, const short* __restrict__ s_list, int base, int m,
    float* __restrict__ out, int c0)
{
    unsigned long long acc[2 * PAIRS];
#pragma unroll
    for (int j = 0; j < 2 * PAIRS; ++j) acc[j] = 0ull;

    // prologue: fill pipeline
    float2 wbuf[PIPE], dbuf[PIPE];
#pragma unroll
    for (int p = 0; p < PIPE; ++p) {
        wbuf[p] = ldg2(wp + (size_t)p * ROWF2);
        dbuf[p] = ldg2(dp + (size_t)p * ROWF2);
    }

    // main: consume k=kk+p, prefetch k=kk+p+PIPE (in-bounds, no clamp)
#pragma unroll 1
    for (int kk = 0; kk < KSEG - PIPE; kk += PIPE) {
#pragma unroll
        for (int p = 0; p < PIPE; ++p) {
            float2 w2 = wbuf[p], d2 = dbuf[p];
            wbuf[p] = ldg2(wp + (size_t)(kk + PIPE + p) * ROWF2);
            dbuf[p] = ldg2(dp + (size_t)(kk + PIPE + p) * ROWF2);
            kstep<PAIRS>(kk + p, w2, d2, xa, acc);
        }
    }
    // drain tail
#pragma unroll
    for (int p = 0; p < PIPE; ++p)
        kstep<PAIRS>(KSEG - PIPE + p, wbuf[p], dbuf[p], xa, acc);

    // merge partials (out pre-initialized with bias by init kernel)
#pragma unroll
    for (int p = 0; p < PAIRS; ++p) {
        float l0, h0, l1, h1;
        unpack2(acc[p],         l0, h0);   // col c0:   samples 2p, 2p+1
        unpack2(acc[PAIRS + p], l1, h1);   // col c0+1
        int i0 = base + 2 * p;
        if (i0 < m) {
            float* o = out + (size_t)s_list[i0] * OUT_F + c0;
            atomicAdd(o, l0);
            atomicAdd(o + 1, l1);
        }
        if (i0 + 1 < m) {
            float* o = out + (size_t)s_list[i0 + 1] * OUT_F + c0;
            atomicAdd(o, h0);
            atomicAdd(o + 1, h1);
        }
    }
}

__global__ void __launch_bounds__(THREADS, 3)
lms_kernel(const float* __restrict__ X,
           const int* __restrict__ hix,
           const int* __restrict__ six,
           const float* __restrict__ W,
           const float* __restrict__ D,
           float* __restrict__ out)
{
    __shared__ int   s_cnt;
    __shared__ short s_list[N_SAMPLES];
    __shared__ __align__(16) float xs[KSEG * CHUNK];   // 4 KB: xs[k][s]

    const int tid = threadIdx.x;
    const int kq  = blockIdx.x;            // k-segment 0..7
    const int g   = blockIdx.y;            // combo 0..127
    const int h   = g >> 2;
    const int sp  = g & 3;
    const int c0  = tid * 2;               // thread's 2 cols (block = all 512)

    // ---- Phase A: build sample list for this combo ----
    if (tid == 0) s_cnt = 0;
    __syncthreads();
    for (int n = tid; n < N_SAMPLES; n += THREADS) {
        if (hix[n] == h && six[n] == sp) {
            int p = atomicAdd(&s_cnt, 1);
            s_list[p] = (short)n;
        }
    }
    __syncthreads();
    const int m = s_cnt;
    if (m == 0) return;                    // uniform across block

    const float2* wp = (const float2*)(W + (size_t)h * (IN_F * OUT_F)
                                         + (size_t)(kq * KSEG) * OUT_F + c0);
    const float2* dp = (const float2*)(D + (size_t)g * (IN_F * OUT_F)
                                         + (size_t)(kq * KSEG) * OUT_F + c0);
    const unsigned xa = (unsigned)__cvta_generic_to_shared(xs);

    // staging: s = tid&15 (sample slot), q = tid>>4 (float4 index 0..15)
    // 16 samples x 16 float4 = 256 loads = one per thread.
    const int s = tid & 15;
    const int q = tid >> 4;

    for (int base = 0; base < m; base += CHUNK) {
        const int  sg    = base + s;
        const bool valid = sg < m;
        float4 v = make_float4(0.f, 0.f, 0.f, 0.f);
        if (valid)
            v = __ldg((const float4*)(X + (size_t)s_list[sg] * IN_F + kq * KSEG) + q);
        const int k0 = q * 4;
        xs[(k0 + 0) * CHUNK + s] = v.x;
        xs[(k0 + 1) * CHUNK + s] = v.y;
        xs[(k0 + 2) * CHUNK + s] = v.z;
        xs[(k0 + 3) * CHUNK + s] = v.w;
        __syncthreads();

        int mc = m - base;
        if (mc > CHUNK) mc = CHUNK;

        if (mc > 8) compute_pass<8>(wp, dp, xa, s_list, base, m, out, c0);
        else        compute_pass<4>(wp, dp, xa, s_list, base, m, out, c0);

        __syncthreads();                   // before next chunk restages xs
    }
}

// Pre-write bias into out: out[n][c] = B[head[n]][c]. 256K float2.
__global__ void __launch_bounds__(THREADS)
init_kernel(const int* __restrict__ hix,
            const float* __restrict__ B,
            float* __restrict__ out)
{
    int i = blockIdx.x * THREADS + threadIdx.x;     // float2 index
    int n  = i >> (9 - 1);                          // i / 256
    int c2 = i & 255;
    int h  = hix[n];
    ((float2*)out)[i] = ((const float2*)B)[h * 256 + c2];
}

extern "C" void kernel_launch(void* const* d_in, const int* in_sizes, int n_in,
                              void* d_out, int out_size)
{
    const float* X   = (const float*)d_in[0];
    const int*   hix = (const int*)d_in[1];
    const int*   six = (const int*)d_in[2];
    const float* W   = (const float*)d_in[3];
    const float* D   = (const float*)d_in[4];
    const float* B   = (const float*)d_in[5];
    float*       out = (float*)d_out;

    // 1) out = bias[head[n]]  (1024*512 floats = 256K float2 -> 1024 blocks)
    init_kernel<<<(N_SAMPLES * OUT_F / 2) / THREADS, THREADS>>>(hix, B, out);
    // 2) accumulate all 8 k-segments per combo
    dim3 grid(KSPLIT, N_COMBO);            // (8, 128) = 1024 blocks
    lms_kernel<<<grid, THREADS>>>(X, hix, six, W, D, out);
}